// round 4
// baseline (speedup 1.0000x reference)
#include <cuda_runtime.h>

// Problem constants
#define O_N   3
#define DK    128
#define DV    512
#define BANK  8192
#define QN    4096
#define BQ    32          // queries per block
#define BN    64          // bank tile
#define NT    (BANK/BN)   // 128 tiles
#define THREADS 256
#define SCALE 0.08838834764831845f   // 1/sqrt(128)

// Shared memory layout (padded for bank-conflict-free access)
struct Smem {
    float Qs[BQ * 129];     // [q][k], pad 129
    float Ks[DK * BN];      // [k][n]
    float Es[BQ * 65];      // [q][n], pad 65 (exp(s) tile)
    float l[BQ];            // per-query sum of exp
    float Vs[BN * 513];     // [n][v], pad 513 (also reused as [v][q] pad-33 bounce buffer)
};

__global__ __launch_bounds__(THREADS, 1)
void attn_fused_kernel(const float* __restrict__ keys,
                       const float* __restrict__ values,
                       const float* __restrict__ q_in,
                       float* __restrict__ out)
{
    extern __shared__ unsigned char smem_raw[];
    Smem& sm = *reinterpret_cast<Smem*>(smem_raw);

    const int tid   = threadIdx.x;
    const int o     = blockIdx.y;
    const int qbase = blockIdx.x * BQ;

    // --- init ---
    if (tid < BQ) sm.l[tid] = 0.0f;

    // Load Q tile: Qs[q][k] <- q_in[k*QN + qbase+q]  (coalesced over q)
    for (int idx = tid; idx < BQ * DK; idx += THREADS) {
        int k = idx >> 5, q = idx & 31;
        sm.Qs[q * 129 + k] = q_in[(size_t)k * QN + qbase + q];
    }

    // S-phase mapping: thread -> 2 queries x 4 banks
    const int sq = tid >> 4;      // 0..15 -> q pair base 2*sq
    const int sn = tid & 15;      // 0..15 -> n quad base 4*sn
    // PV mapping: warp = 4-query group, lanes over v (strided)
    const int tq = tid >> 5;      // 0..7  -> q quad base 4*tq
    const int tv = tid & 31;      // 0..31 -> v = tv + 32*j

    float acc[4][16];
#pragma unroll
    for (int i = 0; i < 4; ++i)
#pragma unroll
        for (int j = 0; j < 16; ++j) acc[i][j] = 0.0f;

    float lpart0 = 0.0f, lpart1 = 0.0f;

    const float* kg = keys   + (size_t)o * DK * BANK;
    const float* vg = values + (size_t)o * DV * BANK;

    for (int t = 0; t < NT; ++t) {
        const int n0 = t * BN;
        __syncthreads();  // previous tile's PV reads of Ks/Vs/Es are done

        // Load K tile [128k x 64n] (float4 over n, coalesced)
        for (int c = tid; c < (DK * BN) / 4; c += THREADS) {
            int k = c >> 4, nq = c & 15;
            const float4 x = *reinterpret_cast<const float4*>(
                kg + (size_t)k * BANK + n0 + 4 * nq);
            *reinterpret_cast<float4*>(&sm.Ks[k * BN + 4 * nq]) = x;
        }
        // Load V tile transposed into Vs[n][v] (pad 513; stride==1 mod 32 -> conflict-free STS)
        for (int c = tid; c < (DV * BN) / 4; c += THREADS) {
            int v = c >> 4, nq = c & 15;
            const float4 x = *reinterpret_cast<const float4*>(
                vg + (size_t)v * BANK + n0 + 4 * nq);
            int nl = 4 * nq;
            sm.Vs[(nl + 0) * 513 + v] = x.x;
            sm.Vs[(nl + 1) * 513 + v] = x.y;
            sm.Vs[(nl + 2) * 513 + v] = x.z;
            sm.Vs[(nl + 3) * 513 + v] = x.w;
        }
        __syncthreads();

        // S = Q K^T for this tile (per-thread 2q x 4n micro-tile over k)
        float s00 = 0.f, s01 = 0.f, s02 = 0.f, s03 = 0.f;
        float s10 = 0.f, s11 = 0.f, s12 = 0.f, s13 = 0.f;
        const float* qr0 = &sm.Qs[(2 * sq + 0) * 129];
        const float* qr1 = &sm.Qs[(2 * sq + 1) * 129];
        const float* kr  = &sm.Ks[4 * sn];
#pragma unroll 8
        for (int k = 0; k < DK; ++k) {
            float a0 = qr0[k], a1 = qr1[k];
            float4 b = *reinterpret_cast<const float4*>(kr + k * BN);
            s00 = fmaf(a0, b.x, s00); s01 = fmaf(a0, b.y, s01);
            s02 = fmaf(a0, b.z, s02); s03 = fmaf(a0, b.w, s03);
            s10 = fmaf(a1, b.x, s10); s11 = fmaf(a1, b.y, s11);
            s12 = fmaf(a1, b.z, s12); s13 = fmaf(a1, b.w, s13);
        }
        // e = exp(scale*s) -> Es[q][n]; accumulate row sums
        {
            float* e0 = &sm.Es[(2 * sq + 0) * 65 + 4 * sn];
            float* e1 = &sm.Es[(2 * sq + 1) * 65 + 4 * sn];
            float v0 = __expf(s00 * SCALE), v1 = __expf(s01 * SCALE);
            float v2 = __expf(s02 * SCALE), v3 = __expf(s03 * SCALE);
            e0[0] = v0; e0[1] = v1; e0[2] = v2; e0[3] = v3;
            lpart0 += (v0 + v1) + (v2 + v3);
            float w0 = __expf(s10 * SCALE), w1 = __expf(s11 * SCALE);
            float w2 = __expf(s12 * SCALE), w3 = __expf(s13 * SCALE);
            e1[0] = w0; e1[1] = w1; e1[2] = w2; e1[3] = w3;
            lpart1 += (w0 + w1) + (w2 + w3);
        }
        __syncthreads();

        // PV: acc[q][v] += e[q][n] * V[n][v]
        const float* prow0 = &sm.Es[(4 * tq + 0) * 65];
        const float* prow1 = &sm.Es[(4 * tq + 1) * 65];
        const float* prow2 = &sm.Es[(4 * tq + 2) * 65];
        const float* prow3 = &sm.Es[(4 * tq + 3) * 65];
#pragma unroll 2
        for (int n = 0; n < BN; ++n) {
            float p0 = prow0[n], p1 = prow1[n], p2 = prow2[n], p3 = prow3[n];
            const float* vr = &sm.Vs[n * 513 + tv];
#pragma unroll
            for (int j = 0; j < 16; ++j) {
                float vv = vr[j * 32];
                acc[0][j] = fmaf(p0, vv, acc[0][j]);
                acc[1][j] = fmaf(p1, vv, acc[1][j]);
                acc[2][j] = fmaf(p2, vv, acc[2][j]);
                acc[3][j] = fmaf(p3, vv, acc[3][j]);
            }
        }
    }

    // Reduce l (one-time; 16 threads per address)
    atomicAdd(&sm.l[2 * sq + 0], lpart0);
    atomicAdd(&sm.l[2 * sq + 1], lpart1);
    __syncthreads();   // all PV reads of Vs done + l complete

    // Bounce acc -> smem as [v][q] (pad 33, conflict-free), then coalesced STG
    float* bb = sm.Vs;  // reuse: need 512*33 = 16896 floats <= 32832
#pragma unroll
    for (int j = 0; j < 16; ++j) {
        int v = tv + 32 * j;
#pragma unroll
        for (int i = 0; i < 4; ++i)
            bb[v * 33 + 4 * tq + i] = acc[i][j];
    }
    __syncthreads();

    const float invl = 1.0f / sm.l[tv];   // lane = query index here
    float* outp = out + (size_t)o * 1024 * QN + qbase + tv;
    for (int v = tq; v < DV; v += 8) {
        outp[(size_t)v * QN] = bb[v * 33 + tv] * invl;
    }
}

// Broadcast q_out into channels [512,1024) of each object (contiguous slabs)
__global__ void copy_qout_kernel(const float* __restrict__ qo,
                                 float* __restrict__ out)
{
    size_t i = (size_t)blockIdx.x * blockDim.x + threadIdx.x;  // over DV*QN/4
    const float4 v = reinterpret_cast<const float4*>(qo)[i];
#pragma unroll
    for (int o = 0; o < O_N; ++o) {
        reinterpret_cast<float4*>(out + (size_t)o * 1024 * QN + (size_t)DV * QN)[i] = v;
    }
}

extern "C" void kernel_launch(void* const* d_in, const int* in_sizes, int n_in,
                              void* d_out, int out_size)
{
    const float* keys   = (const float*)d_in[0];  // [3,128,8192]
    const float* values = (const float*)d_in[1];  // [3,512,8192]
    const float* q_in   = (const float*)d_in[2];  // [1,128,4096]
    const float* q_out  = (const float*)d_in[3];  // [1,512,4096]
    float* out = (float*)d_out;                   // [1,3,1024,4096]

    (void)cudaFuncSetAttribute(attn_fused_kernel,
                               cudaFuncAttributeMaxDynamicSharedMemorySize,
                               (int)sizeof(Smem));

    dim3 grid(QN / BQ, O_N);
    attn_fused_kernel<<<grid, THREADS, sizeof(Smem)>>>(keys, values, q_in, out);

    const int n4 = (DV * QN) / 4;  // 524288 float4
    copy_qout_kernel<<<n4 / 256, 256>>>(q_out, out);
}

// round 6
// speedup vs baseline: 5.6470x; 5.6470x over previous
#include <cuda_runtime.h>
#include <cuda_bf16.h>
#include <cstdint>

// ---------------- problem constants ----------------
#define O_N   3
#define DK    128
#define DV    512
#define BANK  8192
#define QN    4096
#define MQ    64             // queries per block
#define BN    64             // bank tile
#define NV    256            // v columns per pass (vpass = blockIdx.z)
#define NT    128            // bank tiles (8192/64)
#define THREADS 256
// 1/sqrt(128) * log2(e), folded into Q so epilogue is bare ex2
#define QSCALE (0.08838834764831845f * 1.4426950408889634f)

// ---------------- smem layout ----------------
// strides in bf16 halves; chosen so (row_stride_bytes/16) mod 8 is odd -> ldmatrix conflict-free
#define QS_STR 136   // 272 B rows
#define KS_STR 136
#define VS_STR 72    // 144 B rows
#define PS_STR 72
// byte offsets
#define QS_OFF    0                        // 64*136*2  = 17408
#define KS_OFF(b) (17408 + (b) * 17408)    // 2 bufs -> 52224
#define VS_OFF(b) (52224 + (b) * 36864)    // 2 bufs -> 125952
#define PS_OFF    125952                   // 64*72*2  = 9216 -> 135168
#define LROW_OFF  135168                   // 64 f32   = 256  -> 135424
#define SMEM_BYTES 135424

// ---------------- helpers ----------------
static __device__ __forceinline__ uint32_t s2u(const void* p) {
    uint32_t a;
    asm("{ .reg .u64 t; cvta.to.shared.u64 t, %1; cvt.u32.u64 %0, t; }" : "=r"(a) : "l"(p));
    return a;
}
static __device__ __forceinline__ uint32_t pack2(float lo, float hi) {   // lo -> low half
    uint32_t r;
    asm("cvt.rn.bf16x2.f32 %0, %1, %2;" : "=r"(r) : "f"(hi), "f"(lo));
    return r;
}
static __device__ __forceinline__ float ex2f(float x) {
    float r; asm("ex2.approx.f32 %0, %1;" : "=f"(r) : "f"(x)); return r;
}
static __device__ __forceinline__ void ldsm4(uint32_t* r, uint32_t addr) {
    asm volatile("ldmatrix.sync.aligned.m8n8.x4.shared.b16 {%0,%1,%2,%3}, [%4];"
                 : "=r"(r[0]), "=r"(r[1]), "=r"(r[2]), "=r"(r[3]) : "r"(addr));
}
static __device__ __forceinline__ void mma16816(float* d, const uint32_t* a,
                                                uint32_t b0, uint32_t b1) {
    asm volatile(
        "mma.sync.aligned.m16n8k16.row.col.f32.bf16.bf16.f32 "
        "{%0,%1,%2,%3}, {%4,%5,%6,%7}, {%8,%9}, {%0,%1,%2,%3};"
        : "+f"(d[0]), "+f"(d[1]), "+f"(d[2]), "+f"(d[3])
        : "r"(a[0]), "r"(a[1]), "r"(a[2]), "r"(a[3]), "r"(b0), "r"(b1));
}

// ---------------- tile loader (all 256 threads) ----------------
static __device__ __forceinline__ void load_tile(unsigned char* smem,
                                                 const float* __restrict__ kg,
                                                 const float* __restrict__ vg,
                                                 int buf, int t, int tid) {
    const int n0 = t * BN;
    unsigned char* ks = smem + KS_OFF(buf);
    unsigned char* vs = smem + VS_OFF(buf);
    // K: gmem keys[k][n] fp32 -> Ks[n][k] bf16 (pairs packed along k)
#pragma unroll
    for (int i = 0; i < 4; ++i) {
        int idx = tid + THREADS * i;
        int k2 = idx >> 4, n4 = (idx & 15) * 4;
        const float4 xlo = *(const float4*)(kg + (size_t)(2 * k2) * BANK + n0 + n4);
        const float4 xhi = *(const float4*)(kg + (size_t)(2 * k2 + 1) * BANK + n0 + n4);
        *(uint32_t*)(ks + ((n4 + 0) * KS_STR + 2 * k2) * 2) = pack2(xlo.x, xhi.x);
        *(uint32_t*)(ks + ((n4 + 1) * KS_STR + 2 * k2) * 2) = pack2(xlo.y, xhi.y);
        *(uint32_t*)(ks + ((n4 + 2) * KS_STR + 2 * k2) * 2) = pack2(xlo.z, xhi.z);
        *(uint32_t*)(ks + ((n4 + 3) * KS_STR + 2 * k2) * 2) = pack2(xlo.w, xhi.w);
    }
    // V: gmem values[v][n] fp32 -> Vs[v][n] bf16 (same orientation, convert only)
#pragma unroll
    for (int i = 0; i < 16; ++i) {
        int idx = tid + THREADS * i;
        int v = idx >> 4, n4 = (idx & 15) * 4;
        const float4 x = *(const float4*)(vg + (size_t)v * BANK + n0 + n4);
        uint2 pk;
        pk.x = pack2(x.x, x.y);
        pk.y = pack2(x.z, x.w);
        *(uint2*)(vs + (v * VS_STR + n4) * 2) = pk;
    }
}

// ---------------- main fused kernel ----------------
__global__ __launch_bounds__(THREADS, 1)
void attn_mma_kernel(const float* __restrict__ keys, const float* __restrict__ values,
                     const float* __restrict__ q_in, float* __restrict__ out) {
    extern __shared__ unsigned char smem[];
    const uint32_t sb = s2u(smem);
    const int tid = threadIdx.x;
    const int l = tid & 31;
    const int wid = tid >> 5;
    const int mw = wid >> 2;          // 0..1 : 32-query group
    const int nw = wid & 3;           // 0..3 : QK n-group (16) / PV v-group (64)
    const int o = blockIdx.y;
    const int q0 = blockIdx.x * MQ;
    const int v0 = blockIdx.z * NV;

    const float* kg = keys + (size_t)o * DK * BANK;
    const float* vg = values + (size_t)o * DV * BANK + (size_t)v0 * BANK;

    if (tid < MQ) *(float*)(smem + LROW_OFF + tid * 4) = 0.0f;

    // Q -> Qs[q][k] bf16, scaled (one-time)
    {
        __nv_bfloat16* qs = (__nv_bfloat16*)(smem + QS_OFF);
#pragma unroll
        for (int i = 0; i < 8; ++i) {
            int idx = tid + THREADS * i;
            int k = idx >> 4, q4 = (idx & 15) * 4;
            const float4 x = *(const float4*)(q_in + (size_t)k * QN + q0 + q4);
            qs[(q4 + 0) * QS_STR + k] = __float2bfloat16(x.x * QSCALE);
            qs[(q4 + 1) * QS_STR + k] = __float2bfloat16(x.y * QSCALE);
            qs[(q4 + 2) * QS_STR + k] = __float2bfloat16(x.z * QSCALE);
            qs[(q4 + 3) * QS_STR + k] = __float2bfloat16(x.w * QSCALE);
        }
    }
    load_tile(smem, kg, vg, 0, 0, tid);
    __syncthreads();

    float acc[2][8][4];
#pragma unroll
    for (int a = 0; a < 2; ++a)
#pragma unroll
        for (int b = 0; b < 8; ++b)
#pragma unroll
            for (int c = 0; c < 4; ++c) acc[a][b][c] = 0.0f;
    float lsum[4] = {0.f, 0.f, 0.f, 0.f};

    // ldmatrix lane address components
    const int aRow = l & 15;             // A frags: rows within m16
    const int aKhi = l >> 4;             // A frags: k-half select
    const int bRow = (l & 7) + ((l >> 4) << 3);  // B frags: rows (n-dim of B^T)
    const int bKhi = (l >> 3) & 1;               // B frags: k-half select

    const uint32_t qsb = sb + QS_OFF + (uint32_t)(((mw * 32 + aRow) * QS_STR + 8 * aKhi) * 2);
    const uint32_t psb = sb + PS_OFF + (uint32_t)(((mw * 32 + aRow) * PS_STR + 8 * aKhi) * 2);
    const int g8 = l >> 2, t2 = (l & 3) * 2;

    for (int g = 0; g < NT; ++g) {
        const int buf = g & 1;
        // ---- QK: S[64q x 64n] ----
        float sc[2][2][4];
#pragma unroll
        for (int a = 0; a < 2; ++a)
#pragma unroll
            for (int b = 0; b < 2; ++b)
#pragma unroll
                for (int c = 0; c < 4; ++c) sc[a][b][c] = 0.0f;
        {
            const uint32_t ksb = sb + KS_OFF(buf) +
                (uint32_t)(((nw * 16 + bRow) * KS_STR + 8 * bKhi) * 2);
#pragma unroll
            for (int s = 0; s < 8; ++s) {
                uint32_t a0[4], a1[4], b[4];
                ldsm4(a0, qsb + s * 32);
                ldsm4(a1, qsb + 16 * QS_STR * 2 + s * 32);
                ldsm4(b, ksb + s * 32);
                mma16816(sc[0][0], a0, b[0], b[1]);
                mma16816(sc[0][1], a0, b[2], b[3]);
                mma16816(sc[1][0], a1, b[0], b[1]);
                mma16816(sc[1][1], a1, b[2], b[3]);
            }
        }
        // ---- exp -> Ps (bf16), lsum partials ----
#pragma unroll
        for (int mf = 0; mf < 2; ++mf)
#pragma unroll
            for (int nf = 0; nf < 2; ++nf) {
                const int col = nw * 16 + nf * 8 + t2;
                const int row = mw * 32 + mf * 16 + g8;
                float p0 = ex2f(sc[mf][nf][0]), p1 = ex2f(sc[mf][nf][1]);
                *(uint32_t*)(smem + PS_OFF + ((size_t)row * PS_STR + col) * 2) = pack2(p0, p1);
                float p2 = ex2f(sc[mf][nf][2]), p3 = ex2f(sc[mf][nf][3]);
                *(uint32_t*)(smem + PS_OFF + ((size_t)(row + 8) * PS_STR + col) * 2) = pack2(p2, p3);
                lsum[mf * 2 + 0] += p0 + p1;
                lsum[mf * 2 + 1] += p2 + p3;
            }
        __syncthreads();
        // ---- PV: acc += P[64q x 64n] * V[64n x 256v] ----
        {
            const uint32_t vsb = sb + VS_OFF(buf) +
                (uint32_t)(((nw * 64 + bRow) * VS_STR + 8 * bKhi) * 2);
#pragma unroll
            for (int s = 0; s < 4; ++s) {
                uint32_t a0[4], a1[4];
                ldsm4(a0, psb + s * 32);
                ldsm4(a1, psb + 16 * PS_STR * 2 + s * 32);
#pragma unroll
                for (int j = 0; j < 4; ++j) {
                    uint32_t b[4];
                    ldsm4(b, vsb + (uint32_t)(j * 16 * VS_STR * 2) + s * 32);
                    mma16816(acc[0][2 * j],     a0, b[0], b[1]);
                    mma16816(acc[0][2 * j + 1], a0, b[2], b[3]);
                    mma16816(acc[1][2 * j],     a1, b[0], b[1]);
                    mma16816(acc[1][2 * j + 1], a1, b[2], b[3]);
                }
            }
        }
        if (g + 1 < NT) load_tile(smem, kg, vg, (g + 1) & 1, g + 1, tid);
        __syncthreads();
    }

    // ---- reduce l across lanes (t bits) then warps (shared atomics) ----
#pragma unroll
    for (int j = 0; j < 4; ++j) {
        lsum[j] += __shfl_xor_sync(0xffffffffu, lsum[j], 1);
        lsum[j] += __shfl_xor_sync(0xffffffffu, lsum[j], 2);
    }
    if ((l & 3) == 0) {
        float* lrow = (float*)(smem + LROW_OFF);
#pragma unroll
        for (int j = 0; j < 4; ++j)
            atomicAdd(&lrow[mw * 32 + (j >> 1) * 16 + g8 + 8 * (j & 1)], lsum[j]);
    }
    __syncthreads();

    // ---- normalize + store ----
    const float* lrow = (const float*)(smem + LROW_OFF);
    float inv[4];
#pragma unroll
    for (int j = 0; j < 4; ++j)
        inv[j] = 1.0f / lrow[mw * 32 + (j >> 1) * 16 + g8 + 8 * (j & 1)];

    float* ob = out + (size_t)o * 1024 * QN + (size_t)v0 * QN + q0;
#pragma unroll
    for (int mf = 0; mf < 2; ++mf)
#pragma unroll
        for (int nf = 0; nf < 8; ++nf) {
            const int col = nw * 64 + nf * 8 + t2;
            const int r0 = mw * 32 + mf * 16 + g8;
            ob[(size_t)col * QN + r0]           = acc[mf][nf][0] * inv[mf * 2];
            ob[(size_t)(col + 1) * QN + r0]     = acc[mf][nf][1] * inv[mf * 2];
            ob[(size_t)col * QN + r0 + 8]       = acc[mf][nf][2] * inv[mf * 2 + 1];
            ob[(size_t)(col + 1) * QN + r0 + 8] = acc[mf][nf][3] * inv[mf * 2 + 1];
        }
}

// ---------------- q_out broadcast (channels [512,1024) per object) ----------------
__global__ void copy_qout_kernel(const float* __restrict__ qo, float* __restrict__ out) {
    size_t i = (size_t)blockIdx.x * blockDim.x + threadIdx.x;  // over DV*QN/4
    const float4 v = reinterpret_cast<const float4*>(qo)[i];
#pragma unroll
    for (int o = 0; o < O_N; ++o)
        reinterpret_cast<float4*>(out + (size_t)o * 1024 * QN + (size_t)DV * QN)[i] = v;
}

extern "C" void kernel_launch(void* const* d_in, const int* in_sizes, int n_in,
                              void* d_out, int out_size) {
    const float* keys   = (const float*)d_in[0];  // [3,128,8192]
    const float* values = (const float*)d_in[1];  // [3,512,8192]
    const float* q_in   = (const float*)d_in[2];  // [1,128,4096]
    const float* q_out  = (const float*)d_in[3];  // [1,512,4096]
    float* out = (float*)d_out;                   // [1,3,1024,4096]

    (void)cudaFuncSetAttribute(attn_mma_kernel,
                               cudaFuncAttributeMaxDynamicSharedMemorySize, SMEM_BYTES);

    dim3 grid(QN / MQ, O_N, DV / NV);   // 64 x 3 x 2 = 384 blocks
    attn_mma_kernel<<<grid, THREADS, SMEM_BYTES>>>(keys, values, q_in, out);

    copy_qout_kernel<<<(DV * QN / 4) / 256, 256>>>(q_out, out);
}

// round 8
// speedup vs baseline: 5.6736x; 1.0047x over previous
#include <cuda_runtime.h>
#include <cuda_bf16.h>
#include <cstdint>

// ---------------- problem constants ----------------
#define O_N   3
#define DK    128
#define DV    512
#define BANK  8192
#define QN    4096
#define MQ    64             // queries per block
#define BN    64             // bank tile
#define NV    256            // v columns per pass (vpass = blockIdx.z)
#define NT    128            // bank tiles (8192/64)
#define THREADS 256
// 1/sqrt(128) * log2(e), folded into Q so epilogue is bare ex2
#define QSCALE (0.08838834764831845f * 1.4426950408889634f)

// ---------------- smem layout ----------------
// strides in bf16 halves; (row_stride_bytes/16) mod 8 odd -> ldmatrix conflict-free
#define QS_STR 136   // 272 B rows
#define KS_STR 136
#define VS_STR 72    // 144 B rows
#define PS_STR 72
#define QS_OFF    0                        // 64*136*2  = 17408
#define KS_OFF(b) (17408 + (b) * 17408)    // 2 bufs -> 52224
#define VS_OFF(b) (52224 + (b) * 36864)    // 2 bufs -> 125952
#define PS_OFF    125952                   // 64*72*2  = 9216 -> 135168
#define LROW_OFF  135168                   // 64 f32   = 256  -> 135424
#define SMEM_BYTES 135424

// ---------------- helpers ----------------
static __device__ __forceinline__ uint32_t s2u(const void* p) {
    uint32_t a;
    asm("{ .reg .u64 t; cvta.to.shared.u64 t, %1; cvt.u32.u64 %0, t; }" : "=r"(a) : "l"(p));
    return a;
}
static __device__ __forceinline__ uint32_t pack2(float lo, float hi) {   // lo -> low half
    uint32_t r;
    asm("cvt.rn.bf16x2.f32 %0, %1, %2;" : "=r"(r) : "f"(hi), "f"(lo));
    return r;
}
static __device__ __forceinline__ float ex2f(float x) {
    float r; asm("ex2.approx.f32 %0, %1;" : "=f"(r) : "f"(x)); return r;
}
static __device__ __forceinline__ void ldsm4(uint32_t* r, uint32_t addr) {
    asm volatile("ldmatrix.sync.aligned.m8n8.x4.shared.b16 {%0,%1,%2,%3}, [%4];"
                 : "=r"(r[0]), "=r"(r[1]), "=r"(r[2]), "=r"(r[3]) : "r"(addr));
}
static __device__ __forceinline__ void mma16816(float* d, const uint32_t* a,
                                                uint32_t b0, uint32_t b1) {
    asm volatile(
        "mma.sync.aligned.m16n8k16.row.col.f32.bf16.bf16.f32 "
        "{%0,%1,%2,%3}, {%4,%5,%6,%7}, {%8,%9}, {%0,%1,%2,%3};"
        : "+f"(d[0]), "+f"(d[1]), "+f"(d[2]), "+f"(d[3])
        : "r"(a[0]), "r"(a[1]), "r"(a[2]), "r"(a[3]), "r"(b0), "r"(b1));
}

// ---------------- tile pipeline: LDG into regs, then cvt+STS ----------------
static __device__ __forceinline__ void prefetch_tile(const float* __restrict__ kg,
                                                     const float* __restrict__ vg,
                                                     int t, int tid,
                                                     float4* kx, float4* vx) {
    const int n0 = t * BN;
#pragma unroll
    for (int i = 0; i < 4; ++i) {
        int idx = tid + THREADS * i;
        int k2 = idx >> 4, n4 = (idx & 15) * 4;
        kx[2 * i]     = *(const float4*)(kg + (size_t)(2 * k2) * BANK + n0 + n4);
        kx[2 * i + 1] = *(const float4*)(kg + (size_t)(2 * k2 + 1) * BANK + n0 + n4);
    }
#pragma unroll
    for (int i = 0; i < 16; ++i) {
        int idx = tid + THREADS * i;
        int v = idx >> 4, n4 = (idx & 15) * 4;
        vx[i] = *(const float4*)(vg + (size_t)v * BANK + n0 + n4);
    }
}

static __device__ __forceinline__ void store_tile(unsigned char* smem, int buf, int tid,
                                                  const float4* kx, const float4* vx) {
    unsigned char* ks = smem + KS_OFF(buf);
    unsigned char* vs = smem + VS_OFF(buf);
    // K: regs fp32 -> Ks[n][k] bf16 (pairs packed along k)
#pragma unroll
    for (int i = 0; i < 4; ++i) {
        int idx = tid + THREADS * i;
        int k2 = idx >> 4, n4 = (idx & 15) * 4;
        const float4 xlo = kx[2 * i], xhi = kx[2 * i + 1];
        *(uint32_t*)(ks + ((n4 + 0) * KS_STR + 2 * k2) * 2) = pack2(xlo.x, xhi.x);
        *(uint32_t*)(ks + ((n4 + 1) * KS_STR + 2 * k2) * 2) = pack2(xlo.y, xhi.y);
        *(uint32_t*)(ks + ((n4 + 2) * KS_STR + 2 * k2) * 2) = pack2(xlo.z, xhi.z);
        *(uint32_t*)(ks + ((n4 + 3) * KS_STR + 2 * k2) * 2) = pack2(xlo.w, xhi.w);
    }
    // V: regs fp32 -> Vs[v][n] bf16
#pragma unroll
    for (int i = 0; i < 16; ++i) {
        int idx = tid + THREADS * i;
        int v = idx >> 4, n4 = (idx & 15) * 4;
        const float4 x = vx[i];
        uint2 pk;
        pk.x = pack2(x.x, x.y);
        pk.y = pack2(x.z, x.w);
        *(uint2*)(vs + (v * VS_STR + n4) * 2) = pk;
    }
}

// ---------------- main fused kernel ----------------
__global__ __launch_bounds__(THREADS)
void attn_mma_kernel(const float* __restrict__ keys, const float* __restrict__ values,
                     const float* __restrict__ q_in, float* __restrict__ out) {
    extern __shared__ unsigned char smem[];
    const uint32_t sb = s2u(smem);
    const int tid = threadIdx.x;
    const int l = tid & 31;
    const int wid = tid >> 5;
    const int mw = wid >> 2;          // 0..1 : 32-query group
    const int nw = wid & 3;           // 0..3 : QK n-group (16) / PV v-group (64)
    const int o = blockIdx.y;
    const int q0 = blockIdx.x * MQ;
    const int v0 = blockIdx.z * NV;

    const float* kg = keys + (size_t)o * DK * BANK;
    const float* vg = values + (size_t)o * DV * BANK + (size_t)v0 * BANK;

    if (tid < MQ) *(float*)(smem + LROW_OFF + tid * 4) = 0.0f;

    // Q -> Qs[q][k] bf16, scaled (one-time)
    {
        __nv_bfloat16* qs = (__nv_bfloat16*)(smem + QS_OFF);
#pragma unroll
        for (int i = 0; i < 8; ++i) {
            int idx = tid + THREADS * i;
            int k = idx >> 4, q4 = (idx & 15) * 4;
            const float4 x = *(const float4*)(q_in + (size_t)k * QN + q0 + q4);
            qs[(q4 + 0) * QS_STR + k] = __float2bfloat16(x.x * QSCALE);
            qs[(q4 + 1) * QS_STR + k] = __float2bfloat16(x.y * QSCALE);
            qs[(q4 + 2) * QS_STR + k] = __float2bfloat16(x.z * QSCALE);
            qs[(q4 + 3) * QS_STR + k] = __float2bfloat16(x.w * QSCALE);
        }
    }
    {
        float4 kx[8], vx[16];
        prefetch_tile(kg, vg, 0, tid, kx, vx);
        store_tile(smem, 0, tid, kx, vx);
    }
    __syncthreads();

    float acc[2][8][4];
#pragma unroll
    for (int a = 0; a < 2; ++a)
#pragma unroll
        for (int b = 0; b < 8; ++b)
#pragma unroll
            for (int c = 0; c < 4; ++c) acc[a][b][c] = 0.0f;
    float lsum[4] = {0.f, 0.f, 0.f, 0.f};

    // ldmatrix lane address components
    const int aRow = l & 15;                     // A frags: rows within m16
    const int aKhi = l >> 4;                     // A frags: k-half select
    const int bRow = (l & 7) + ((l >> 4) << 3);  // B frags: rows (n-dim of B^T)
    const int bKhi = (l >> 3) & 1;               // B frags: k-half select

    const uint32_t qsb = sb + QS_OFF + (uint32_t)(((mw * 32 + aRow) * QS_STR + 8 * aKhi) * 2);
    const uint32_t psb = sb + PS_OFF + (uint32_t)(((mw * 32 + aRow) * PS_STR + 8 * aKhi) * 2);
    const int g8 = l >> 2, t2 = (l & 3) * 2;

    for (int g = 0; g < NT; ++g) {
        const int buf = g & 1;
        // ---- prefetch tile g+1 into registers (latency spans QK+exp) ----
        float4 kx[8], vx[16];
        if (g + 1 < NT) prefetch_tile(kg, vg, g + 1, tid, kx, vx);
        // ---- QK: S[64q x 64n] ----
        float sc[2][2][4];
#pragma unroll
        for (int a = 0; a < 2; ++a)
#pragma unroll
            for (int b = 0; b < 2; ++b)
#pragma unroll
                for (int c = 0; c < 4; ++c) sc[a][b][c] = 0.0f;
        {
            const uint32_t ksb = sb + KS_OFF(buf) +
                (uint32_t)(((nw * 16 + bRow) * KS_STR + 8 * bKhi) * 2);
#pragma unroll
            for (int s = 0; s < 8; ++s) {
                uint32_t a0[4], a1[4], b[4];
                ldsm4(a0, qsb + s * 32);
                ldsm4(a1, qsb + 16 * QS_STR * 2 + s * 32);
                ldsm4(b, ksb + s * 32);
                mma16816(sc[0][0], a0, b[0], b[1]);
                mma16816(sc[0][1], a0, b[2], b[3]);
                mma16816(sc[1][0], a1, b[0], b[1]);
                mma16816(sc[1][1], a1, b[2], b[3]);
            }
        }
        // ---- exp -> Ps (bf16), lsum partials ----
#pragma unroll
        for (int mf = 0; mf < 2; ++mf)
#pragma unroll
            for (int nf = 0; nf < 2; ++nf) {
                const int col = nw * 16 + nf * 8 + t2;
                const int row = mw * 32 + mf * 16 + g8;
                float p0 = ex2f(sc[mf][nf][0]), p1 = ex2f(sc[mf][nf][1]);
                *(uint32_t*)(smem + PS_OFF + ((size_t)row * PS_STR + col) * 2) = pack2(p0, p1);
                float p2 = ex2f(sc[mf][nf][2]), p3 = ex2f(sc[mf][nf][3]);
                *(uint32_t*)(smem + PS_OFF + ((size_t)(row + 8) * PS_STR + col) * 2) = pack2(p2, p3);
                lsum[mf * 2 + 0] += p0 + p1;
                lsum[mf * 2 + 1] += p2 + p3;
            }
        // ---- drain prefetched tile into the spare buffer ----
        if (g + 1 < NT) store_tile(smem, (g + 1) & 1, tid, kx, vx);
        __syncthreads();
        // ---- PV: acc += P[64q x 64n] * V[64n x 256v] ----
        {
            const uint32_t vsb = sb + VS_OFF(buf) +
                (uint32_t)(((nw * 64 + bRow) * VS_STR + 8 * bKhi) * 2);
#pragma unroll
            for (int s = 0; s < 4; ++s) {
                uint32_t a0[4], a1[4];
                ldsm4(a0, psb + s * 32);
                ldsm4(a1, psb + 16 * PS_STR * 2 + s * 32);
#pragma unroll
                for (int j = 0; j < 4; ++j) {
                    uint32_t b[4];
                    ldsm4(b, vsb + (uint32_t)(j * 16 * VS_STR * 2) + s * 32);
                    mma16816(acc[0][2 * j],     a0, b[0], b[1]);
                    mma16816(acc[0][2 * j + 1], a0, b[2], b[3]);
                    mma16816(acc[1][2 * j],     a1, b[0], b[1]);
                    mma16816(acc[1][2 * j + 1], a1, b[2], b[3]);
                }
            }
        }
        __syncthreads();
    }

    // ---- reduce l across lanes (t bits) then warps (shared atomics) ----
#pragma unroll
    for (int j = 0; j < 4; ++j) {
        lsum[j] += __shfl_xor_sync(0xffffffffu, lsum[j], 1);
        lsum[j] += __shfl_xor_sync(0xffffffffu, lsum[j], 2);
    }
    if ((l & 3) == 0) {
        float* lrow = (float*)(smem + LROW_OFF);
#pragma unroll
        for (int j = 0; j < 4; ++j)
            atomicAdd(&lrow[mw * 32 + (j >> 1) * 16 + g8 + 8 * (j & 1)], lsum[j]);
    }
    __syncthreads();

    // ---- normalize + store ----
    const float* lrow = (const float*)(smem + LROW_OFF);
    float inv[4];
#pragma unroll
    for (int j = 0; j < 4; ++j)
        inv[j] = 1.0f / lrow[mw * 32 + (j >> 1) * 16 + g8 + 8 * (j & 1)];

    float* ob = out + (size_t)o * 1024 * QN + (size_t)v0 * QN + q0;
#pragma unroll
    for (int mf = 0; mf < 2; ++mf)
#pragma unroll
        for (int nf = 0; nf < 8; ++nf) {
            const int col = nw * 64 + nf * 8 + t2;
            const int r0 = mw * 32 + mf * 16 + g8;
            ob[(size_t)col * QN + r0]           = acc[mf][nf][0] * inv[mf * 2];
            ob[(size_t)(col + 1) * QN + r0]     = acc[mf][nf][1] * inv[mf * 2];
            ob[(size_t)col * QN + r0 + 8]       = acc[mf][nf][2] * inv[mf * 2 + 1];
            ob[(size_t)(col + 1) * QN + r0 + 8] = acc[mf][nf][3] * inv[mf * 2 + 1];
        }
}

// ---------------- q_out broadcast (channels [512,1024) per object) ----------------
__global__ void copy_qout_kernel(const float* __restrict__ qo, float* __restrict__ out) {
    size_t i = (size_t)blockIdx.x * blockDim.x + threadIdx.x;  // over DV*QN/4
    const float4 v = reinterpret_cast<const float4*>(qo)[i];
#pragma unroll
    for (int o = 0; o < O_N; ++o)
        reinterpret_cast<float4*>(out + (size_t)o * 1024 * QN + (size_t)DV * QN)[i] = v;
}

extern "C" void kernel_launch(void* const* d_in, const int* in_sizes, int n_in,
                              void* d_out, int out_size) {
    const float* keys   = (const float*)d_in[0];  // [3,128,8192]
    const float* values = (const float*)d_in[1];  // [3,512,8192]
    const float* q_in   = (const float*)d_in[2];  // [1,128,4096]
    const float* q_out  = (const float*)d_in[3];  // [1,512,4096]
    float* out = (float*)d_out;                   // [1,3,1024,4096]

    (void)cudaFuncSetAttribute(attn_mma_kernel,
                               cudaFuncAttributeMaxDynamicSharedMemorySize, SMEM_BYTES);

    dim3 grid(QN / MQ, O_N, DV / NV);   // 64 x 3 x 2 = 384 blocks
    attn_mma_kernel<<<grid, THREADS, SMEM_BYTES>>>(keys, values, q_in, out);

    copy_qout_kernel<<<(DV * QN / 4) / 256, 256>>>(q_out, out);
}